// round 15
// baseline (speedup 1.0000x reference)
#include <cuda_runtime.h>
#include <math.h>

#define NT 365
#define NTP 368          // 23 chunks of 16
#define NCHUNK 23
#define CH 16
#define RPITCH 36        // reduce-buffer row pitch
#define FPITCH 369       // sForc row pitch (float4)
#define PPITCH 369       // sPart row pitch
#define NS 1024
#define NH 64
#define NG 32
#define NW 514
#define SPB_MAX 8
#define THREADS 512
#define NBLK 147         // 146 blocks x 7 sites + 1 block x 2 sites

__device__ __forceinline__ float sigm(float x) { return 1.0f / (1.0f + expf(-x)); }

// Dynamic smem layout (bytes):
#define OFF_BUF   (SPB_MAX * FPITCH * 16)          // 47232
#define OFF_PART  (OFF_BUF + 16 * CH * RPITCH * 4) // +36864
#define OFF_XC    (OFF_PART + 16 * PPITCH * 4)     // +23616
#define OFF_TAIL  (OFF_XC + SPB_MAX * NG * 4)      // +1024
#define SMEM_TOTAL (OFF_TAIL + 160)

extern __shared__ __align__(16) char smemRaw[];

__global__ void __launch_bounds__(THREADS)
waternet_kernel(const float* __restrict__ x,
                const float* __restrict__ xc,
                const float* __restrict__ fc_w,
                const float* __restrict__ fc_b,
                float* __restrict__ out) {
    float4* sForc = reinterpret_cast<float4*>(smemRaw);                 // [SPB][FPITCH]
    float*  sBuf  = reinterpret_cast<float*>(smemRaw + OFF_BUF);        // [16][CH*RPITCH]
    float4* sFW4  = reinterpret_cast<float4*>(smemRaw + OFF_BUF);       // [64][9] overlay
    float*  sPart = reinterpret_cast<float*>(smemRaw + OFF_PART);       // [16][PPITCH]
    float*  sXc   = reinterpret_cast<float*>(smemRaw + OFF_XC);         // [SPB][NG]
    float*  sQb   = reinterpret_cast<float*>(smemRaw + OFF_TAIL);       // [8]
    float*  sMax  = sQb + 8;                                            // [8][2]
    float*  sSum  = sMax + 16;                                          // [8][2]

    const int tid  = threadIdx.x;
    const int warp = tid >> 5;          // 0..15
    const int lane = tid & 31;
    const int si   = warp >> 1;         // site in block 0..7
    const int w2   = warp & 1;          // pair half
    const int bid  = blockIdx.x;
    const int s0   = bid * 7;           // last block: s0 = 1022
    const int spb  = (bid < NBLK - 1) ? 7 : (NS - 7 * (NBLK - 1));   // 7 or 2
    const int s    = s0 + si;           // valid when si < spb
    const int h    = w2 * 32 + lane;    // 0..63
    const bool act = (si < spb);

    // ---- preload this thread's fc_w float4 for all 8 GEMM chunks (MLP=8) ----
    const float4* fw4 = reinterpret_cast<const float4*>(fc_w);
    const int jl = tid >> 3;            // row within chunk (0..63)
    const int qq = tid & 7;             // float4 within row
    float4 myfw[8];
    #pragma unroll
    for (int c = 0; c < 8; ++c)
        myfw[c] = fw4[(c * 64 + jl) * 8 + qq];

    // ---- stage xc (coalesced; overlaps fc_w LDG latency) ----
    if (tid < SPB_MAX * NG) {
        const int sl = tid >> 5;
        sXc[tid] = (sl < spb) ? xc[(s0 + sl) * NG + (tid & 31)] : 0.0f;
    }

    // ---- forcing staging: coalesced (consecutive sites per t) ----
    const float4* x4 = reinterpret_cast<const float4*>(x);
    {
        const int sl = tid & 7;
        for (int t = tid >> 3; t < NTP; t += 64) {
            if (sl < spb) {
                float4 o = make_float4(0.f, 0.f, 0.f, 0.f);
                if (t < NT) {
                    float4 xi = x4[t * NS + s0 + sl];
                    float P = xi.x, E = xi.y, T1 = xi.z, T2 = xi.w;
                    float Ta = (T1 + T2) * 0.5f;
                    bool valid  = (T1 < 0.0f) && (T2 > 0.0f);
                    float denom = valid ? (T2 - T1) : 1.0f;
                    float ratio = valid ? (T1 + T2) / denom : 0.0f;
                    ratio = fminf(fmaxf(ratio, -0.999999f), 0.999999f);
                    float rP = 1.0f - acosf(ratio) / 3.1415f;
                    if (T1 >= 0.0f) rP = 1.0f;
                    if (T2 <= 0.0f) rP = 0.0f;
                    o.x = (1.0f - rP) * P;      // Ps
                    o.y = rP * P;               // Pl
                    o.z = fmaxf(Ta, 0.0f);      // ReLU(Ta)
                    o.w = E;
                }
                sForc[sl * FPITCH + t] = o;
            }
        }
    }
    __syncthreads();

    // ---- GEMM: per chunk STS(reg) -> sync -> dot-from-smem -> sync ----
    const float4* xs4 = reinterpret_cast<const float4*>(sXc + si * NG);
    float wv[8];
    #pragma unroll
    for (int c = 0; c < 8; ++c) {
        sFW4[jl * 9 + qq] = myfw[c];
        __syncthreads();
        float acc = 0.0f;
        if (act) {
            #pragma unroll
            for (int q = 0; q < 8; ++q) {
                const float4 v  = sFW4[h * 9 + q];
                const float4 xv = xs4[q];          // warp-broadcast LDS
                acc += v.x * xv.x + v.y * xv.y + v.z * xv.z + v.w * xv.w;
            }
        }
        wv[c] = acc;
        __syncthreads();
    }
    #pragma unroll
    for (int c = 0; c < 8; ++c) wv[c] += fc_b[c * NH + h];

    // ---- qb: warp 0 lanes 0..spb-1, one site each ----
    if (warp == 0 && lane < spb) {
        float acc = 0.0f;
        const float* xr = sXc + lane * NG;
        #pragma unroll
        for (int q = 0; q < 8; ++q) {
            float4 v = fw4[513 * 8 + q];           // L2-hot broadcast
            acc += v.x * xr[q * 4 + 0] + v.y * xr[q * 4 + 1]
                 + v.z * xr[q * 4 + 2] + v.w * xr[q * 4 + 3];
        }
        sQb[lane] = fmaxf(acc + fc_b[513], 0.0f) * (1.0f / 64.0f);
    }

    // ---- activations ----
    const float gm   = expf(wv[0]) + 1.0f;
    const float nge  = -2.0f * sigm(wv[1]);
    const float go   = sigm(wv[2]);
    const float gl   = expf(2.0f * wv[3]);
    const float araw = wv[4];
    const float gb   = sigm(wv[5]);
    const float kb   = sigm(wv[6]) * 0.1f;
    const float gi   = sigm(wv[7]);
    const float kb1  = 1.0f - kb;

    // ---- softmax over the site's 64 h (cross-pair via smem) ----
    float m = araw;
    #pragma unroll
    for (int o = 16; o; o >>= 1) m = fmaxf(m, __shfl_xor_sync(0xffffffffu, m, o));
    if (lane == 0) sMax[si * 2 + w2] = m;
    __syncthreads();
    m = fmaxf(sMax[si * 2], sMax[si * 2 + 1]);
    float e = expf(araw - m);
    float ssum = e;
    #pragma unroll
    for (int o = 16; o; o >>= 1) ssum += __shfl_xor_sync(0xffffffffu, ssum, o);
    if (lane == 0) sSum[si * 2 + w2] = ssum;
    __syncthreads();
    const float ga = e / (sSum[si * 2] + sSum[si * 2 + 1]);

    const float chc  = go * (1.0f - gb) * ga - ga;
    const float cg   = kb * ga;
    const float gogb = go * gb;

    // ---- sequential scan: per-warp, no block barriers; idle warps skip ----
    if (act) {
        float* buf = sBuf + warp * (CH * RPITCH);
        const float4* forc = sForc + si * FPITCH;
        float* part = sPart + warp * PPITCH;
        const int rt = lane >> 1;
        const int rq = lane & 1;

        float S0 = 0.0f, H0 = 0.0f, G0 = 0.0f;

        for (int c = 0; c < NCHUNK; ++c) {
            const float4* fp = forc + c * CH;
            float yv[CH];
            #pragma unroll
            for (int tt = 0; tt < CH; ++tt) {
                float4 f  = fp[tt];                      // broadcast LDS.128
                float Sm  = fminf(S0, f.z * gm);
                float At  = fmaf(f.w, nge, f.y * gi);    // Pl*gi - E*ge
                float H   = fmaxf(H0 + Sm + At, 0.0f);
                float Hc  = fminf(H, gl);
                float t1  = fmaf(-go, Hc, H);
                float g2  = fmaf(Hc, gogb, G0);
                H0 = fminf(t1, gl);
                G0 = g2 * kb1;
                S0 = (S0 - Sm) + f.x;
                float y = H * ga;
                y = fmaf(Hc, chc, y);
                y = fmaf(g2, cg, y);
                yv[tt] = y;
            }
            #pragma unroll
            for (int tt = 0; tt < CH; ++tt)
                buf[tt * RPITCH + lane] = yv[tt];        // burst, conflict-free
            __syncwarp();
            const float4* rr = reinterpret_cast<const float4*>(buf + rt * RPITCH + rq * 16);
            float4 v0 = rr[0], v1 = rr[1], v2 = rr[2], v3 = rr[3];
            float p = (((v0.x + v0.y) + (v0.z + v0.w)) + ((v1.x + v1.y) + (v1.z + v1.w)))
                    + (((v2.x + v2.y) + (v2.z + v2.w)) + ((v3.x + v3.y) + (v3.z + v3.w)));
            p += __shfl_xor_sync(0xffffffffu, p, 1);
            if (rq == 0) part[c * CH + rt] = p;
            __syncwarp();
        }
    }

    // ---- epilogue: combine pair halves + qb; near-coalesced stores ----
    __syncthreads();
    {
        const int sl = tid & 7;
        if (sl < spb) {
            for (int t = tid >> 3; t < NT; t += 64) {
                const float v = sPart[(2 * sl) * PPITCH + t]
                              + sPart[(2 * sl + 1) * PPITCH + t]
                              + sQb[sl];
                out[t * NS + s0 + sl] = v;
            }
        }
    }
}

// ---------------------------------------------------------------------------
extern "C" void kernel_launch(void* const* d_in, const int* in_sizes, int n_in,
                              void* d_out, int out_size) {
    const float* x    = (const float*)d_in[0];   // [NT, NS, 4]
    const float* xc   = (const float*)d_in[1];   // [NS, NG]
    const float* fc_w = (const float*)d_in[2];   // [NW, NG]
    const float* fc_b = (const float*)d_in[3];   // [NW]
    float* out = (float*)d_out;                  // [NT, NS]

    static int configured = 0;
    if (!configured) {
        cudaFuncSetAttribute(waternet_kernel,
                             cudaFuncAttributeMaxDynamicSharedMemorySize,
                             SMEM_TOTAL);
        configured = 1;
    }
    waternet_kernel<<<NBLK, THREADS, SMEM_TOTAL>>>(x, xc, fc_w, fc_b, out);
}